// round 2
// baseline (speedup 1.0000x reference)
#include <cuda_runtime.h>

// ---------------------------------------------------------------------------
// EBTAttention: hidden(2,2048,2048) -> QKV proj -> RoPE(q,k) -> softmax attn
//               -> O proj. All fp32.
// R1: SIMT fp32 tiled GEMMs (128x128x8, 256 thr, 8x8 per thread).
// ---------------------------------------------------------------------------

#define BATCH 2
#define SEQ   2048
#define HID   2048
#define NH    16
#define NKV   16
#define HD    128
#define QKV_COLS ((NH + 2 * NKV) * HD)   // 6144
#define ROWS  (BATCH * SEQ)              // 4096
#define OCOLS (NH * HD)                  // 2048

static __device__ __align__(16) float g_qkv[(size_t)ROWS * QKV_COLS];          // ~100 MB
static __device__ __align__(16) float g_scores[(size_t)BATCH * NH * SEQ * SEQ]; // ~536 MB
static __device__ __align__(16) float g_attnout[(size_t)ROWS * OCOLS];          // ~33 MB

__constant__ float c_scale = 0.08838834764831845f; // 1/sqrt(128)

// ---------------------------------------------------------------------------
// GEMM NT body: C[m,n] = alpha * sum_k A[m*lda+k] * B[n*ldb+k]
// Tile 128x128, BK=8, 256 threads, 8x8 per-thread micro-tile.
// Requires M,N multiples of 128, K multiple of 8, 16B-aligned rows.
// ---------------------------------------------------------------------------
__device__ __forceinline__ void gemm_nt_body(
    const float* __restrict__ A, const float* __restrict__ B, float* __restrict__ C,
    int K, int lda, int ldb, int ldc, float alpha)
{
    __shared__ float As[8][128];
    __shared__ float Bs[8][128];

    const int tid = threadIdx.x;
    const int tx = tid & 15;        // 0..15 -> N
    const int ty = tid >> 4;        // 0..15 -> M
    const int mrow0 = blockIdx.y * 128;
    const int ncol0 = blockIdx.x * 128;

    float acc[8][8];
#pragma unroll
    for (int i = 0; i < 8; i++)
#pragma unroll
        for (int j = 0; j < 8; j++) acc[i][j] = 0.0f;

    const int lrow = tid >> 1;       // 0..127
    const int lk   = (tid & 1) * 4;  // 0 or 4
    const float* Ap = A + (size_t)(mrow0 + lrow) * lda + lk;
    const float* Bp = B + (size_t)(ncol0 + lrow) * ldb + lk;

    for (int k0 = 0; k0 < K; k0 += 8) {
        float4 a = *(const float4*)(Ap + k0);
        float4 b = *(const float4*)(Bp + k0);
        As[lk + 0][lrow] = a.x; As[lk + 1][lrow] = a.y;
        As[lk + 2][lrow] = a.z; As[lk + 3][lrow] = a.w;
        Bs[lk + 0][lrow] = b.x; Bs[lk + 1][lrow] = b.y;
        Bs[lk + 2][lrow] = b.z; Bs[lk + 3][lrow] = b.w;
        __syncthreads();

#pragma unroll
        for (int kk = 0; kk < 8; kk++) {
            float ar[8], br[8];
            *(float4*)(ar)     = *(const float4*)&As[kk][ty * 8];
            *(float4*)(ar + 4) = *(const float4*)&As[kk][ty * 8 + 4];
            *(float4*)(br)     = *(const float4*)&Bs[kk][tx * 8];
            *(float4*)(br + 4) = *(const float4*)&Bs[kk][tx * 8 + 4];
#pragma unroll
            for (int i = 0; i < 8; i++)
#pragma unroll
                for (int j = 0; j < 8; j++)
                    acc[i][j] = fmaf(ar[i], br[j], acc[i][j]);
        }
        __syncthreads();
    }

#pragma unroll
    for (int i = 0; i < 8; i++) {
        float* Cp = C + (size_t)(mrow0 + ty * 8 + i) * ldc + ncol0 + tx * 8;
        float4 c0, c1;
        c0.x = alpha * acc[i][0]; c0.y = alpha * acc[i][1];
        c0.z = alpha * acc[i][2]; c0.w = alpha * acc[i][3];
        c1.x = alpha * acc[i][4]; c1.y = alpha * acc[i][5];
        c1.z = alpha * acc[i][6]; c1.w = alpha * acc[i][7];
        *(float4*)(Cp)     = c0;
        *(float4*)(Cp + 4) = c1;
    }
}

// ---------------------------------------------------------------------------
// GEMM NN body: C[m,n] = alpha * sum_k A[m*lda+k] * B[k*ldb+n]
// ---------------------------------------------------------------------------
__device__ __forceinline__ void gemm_nn_body(
    const float* __restrict__ A, const float* __restrict__ B, float* __restrict__ C,
    int K, int lda, int ldb, int ldc, float alpha)
{
    __shared__ float As[8][128];
    __shared__ float Bs[8][128];

    const int tid = threadIdx.x;
    const int tx = tid & 15;
    const int ty = tid >> 4;
    const int mrow0 = blockIdx.y * 128;
    const int ncol0 = blockIdx.x * 128;

    float acc[8][8];
#pragma unroll
    for (int i = 0; i < 8; i++)
#pragma unroll
        for (int j = 0; j < 8; j++) acc[i][j] = 0.0f;

    const int lrow = tid >> 1;       // 0..127 (A rows)
    const int lk   = (tid & 1) * 4;  // 0 or 4
    const float* Ap = A + (size_t)(mrow0 + lrow) * lda + lk;

    const int lkB  = tid >> 5;        // 0..7 (B k-row)
    const int lcol = (tid & 31) * 4;  // 0..124

    for (int k0 = 0; k0 < K; k0 += 8) {
        float4 a = *(const float4*)(Ap + k0);
        float4 b = *(const float4*)(B + (size_t)(k0 + lkB) * ldb + ncol0 + lcol);
        As[lk + 0][lrow] = a.x; As[lk + 1][lrow] = a.y;
        As[lk + 2][lrow] = a.z; As[lk + 3][lrow] = a.w;
        *(float4*)&Bs[lkB][lcol] = b;
        __syncthreads();

#pragma unroll
        for (int kk = 0; kk < 8; kk++) {
            float ar[8], br[8];
            *(float4*)(ar)     = *(const float4*)&As[kk][ty * 8];
            *(float4*)(ar + 4) = *(const float4*)&As[kk][ty * 8 + 4];
            *(float4*)(br)     = *(const float4*)&Bs[kk][tx * 8];
            *(float4*)(br + 4) = *(const float4*)&Bs[kk][tx * 8 + 4];
#pragma unroll
            for (int i = 0; i < 8; i++)
#pragma unroll
                for (int j = 0; j < 8; j++)
                    acc[i][j] = fmaf(ar[i], br[j], acc[i][j]);
        }
        __syncthreads();
    }

#pragma unroll
    for (int i = 0; i < 8; i++) {
        float* Cp = C + (size_t)(mrow0 + ty * 8 + i) * ldc + ncol0 + tx * 8;
        float4 c0, c1;
        c0.x = alpha * acc[i][0]; c0.y = alpha * acc[i][1];
        c0.z = alpha * acc[i][2]; c0.w = alpha * acc[i][3];
        c1.x = alpha * acc[i][4]; c1.y = alpha * acc[i][5];
        c1.z = alpha * acc[i][6]; c1.w = alpha * acc[i][7];
        *(float4*)(Cp)     = c0;
        *(float4*)(Cp + 4) = c1;
    }
}

// ---------------------------------------------------------------------------
// Kernels
// ---------------------------------------------------------------------------

// QKV projection: g_qkv[4096,6144] = hidden[4096,2048] @ w_qkv[6144,2048]^T
__global__ void __launch_bounds__(256) k_qkv(const float* __restrict__ hidden,
                                             const float* __restrict__ wqkv)
{
    gemm_nt_body(hidden, wqkv, g_qkv, HID, HID, HID, QKV_COLS, 1.0f);
}

// RoPE on q (heads 0..15) and k (heads 16..31) sections of g_qkv, in place.
// One thread per (row, head, d<64) pair.
__global__ void __launch_bounds__(256) k_rope(const float* __restrict__ cosp,
                                              const float* __restrict__ sinp)
{
    int idx = blockIdx.x * blockDim.x + threadIdx.x; // ROWS*32*64
    int d    = idx & 63;
    int head = (idx >> 6) & 31;
    int row  = idx >> 11;
    int s    = row & (SEQ - 1);

    float* p = g_qkv + (size_t)row * QKV_COLS + head * HD;
    float x1 = p[d];
    float x2 = p[d + 64];
    float c1 = cosp[s * HD + d],      s1 = sinp[s * HD + d];
    float c2 = cosp[s * HD + d + 64], s2 = sinp[s * HD + d + 64];
    p[d]      = x1 * c1 - x2 * s1;   // x*cos + (-x2)*sin
    p[d + 64] = x2 * c2 + x1 * s2;   // x*cos + ( x1)*sin
}

// scores[z=b*16+h] = scale * Q_h K_h^T   (2048x2048, K=128)
__global__ void __launch_bounds__(256) k_scores()
{
    int z = blockIdx.z;
    int b = z >> 4;
    int h = z & 15;
    const float* base = g_qkv + (size_t)b * SEQ * QKV_COLS;
    gemm_nt_body(base + h * HD,            // Q
                 base + (NH + h) * HD,     // K
                 g_scores + (size_t)z * SEQ * SEQ,
                 HD, QKV_COLS, QKV_COLS, SEQ, c_scale);
}

// Row softmax over last dim (2048). One 256-thread block per row.
__global__ void __launch_bounds__(256) k_softmax()
{
    float* p = g_scores + (size_t)blockIdx.x * SEQ;
    const int tid = threadIdx.x;
    __shared__ float red[8];

    // max
    float m = -1e30f;
    for (int j = tid; j < SEQ; j += 256) m = fmaxf(m, p[j]);
#pragma unroll
    for (int o = 16; o; o >>= 1) m = fmaxf(m, __shfl_xor_sync(0xffffffffu, m, o));
    if ((tid & 31) == 0) red[tid >> 5] = m;
    __syncthreads();
    if (tid < 32) {
        float v = (tid < 8) ? red[tid] : -1e30f;
#pragma unroll
        for (int o = 4; o; o >>= 1) v = fmaxf(v, __shfl_xor_sync(0xffffffffu, v, o));
        if (tid == 0) red[0] = v;
    }
    __syncthreads();
    m = red[0];
    __syncthreads();

    // exp + sum
    float sum = 0.0f;
    for (int j = tid; j < SEQ; j += 256) {
        float e = __expf(p[j] - m);
        p[j] = e;
        sum += e;
    }
#pragma unroll
    for (int o = 16; o; o >>= 1) sum += __shfl_xor_sync(0xffffffffu, sum, o);
    if ((tid & 31) == 0) red[tid >> 5] = sum;
    __syncthreads();
    if (tid < 32) {
        float v = (tid < 8) ? red[tid] : 0.0f;
#pragma unroll
        for (int o = 4; o; o >>= 1) v += __shfl_xor_sync(0xffffffffu, v, o);
        if (tid == 0) red[0] = v;
    }
    __syncthreads();
    float inv = 1.0f / red[0];

    for (int j = tid; j < SEQ; j += 256) p[j] *= inv;
}

// attnout[b, i, h*128 + d] = sum_j P[z,i,j] * V[b,j,(32+h)*128 + d]
__global__ void __launch_bounds__(256) k_pv()
{
    int z = blockIdx.z;
    int b = z >> 4;
    int h = z & 15;
    gemm_nn_body(g_scores + (size_t)z * SEQ * SEQ,
                 g_qkv + (size_t)b * SEQ * QKV_COLS + (NH + NKV + h) * HD,
                 g_attnout + (size_t)b * SEQ * OCOLS + h * HD,
                 SEQ, SEQ, QKV_COLS, OCOLS, 1.0f);
}

// out[4096,2048] = attnout[4096,2048] @ w_o[2048,2048]^T
__global__ void __launch_bounds__(256) k_oproj(const float* __restrict__ wo,
                                               float* __restrict__ out)
{
    gemm_nt_body(g_attnout, wo, out, OCOLS, OCOLS, OCOLS, HID, 1.0f);
}

// ---------------------------------------------------------------------------
// Launch
// ---------------------------------------------------------------------------
extern "C" void kernel_launch(void* const* d_in, const int* in_sizes, int n_in,
                              void* d_out, int out_size)
{
    const float* hidden = (const float*)d_in[0];
    const float* cosp   = (const float*)d_in[1];
    const float* sinp   = (const float*)d_in[2];
    const float* wqkv   = (const float*)d_in[3];
    const float* wo     = (const float*)d_in[4];
    float* out = (float*)d_out;

    dim3 blk(256);

    // 1) QKV projection: 4096 x 6144 x 2048
    k_qkv<<<dim3(QKV_COLS / 128, ROWS / 128), blk>>>(hidden, wqkv);

    // 2) RoPE on q,k: ROWS*32*64 threads
    k_rope<<<(ROWS * 32 * 64) / 256, blk>>>(cosp, sinp);

    // 3) scores: 32 batched 2048x2048x128 GEMMs
    k_scores<<<dim3(SEQ / 128, SEQ / 128, BATCH * NH), blk>>>();

    // 4) softmax: one block per row
    k_softmax<<<BATCH * NH * SEQ, blk>>>();

    // 5) PV: 32 batched 2048x128x2048 GEMMs
    k_pv<<<dim3(1, SEQ / 128, BATCH * NH), blk>>>();

    // 6) O projection: 4096 x 2048 x 2048
    k_oproj<<<dim3(OCOLS / 128, ROWS / 128), blk>>>(wo, out);
}

// round 4
// speedup vs baseline: 2.1745x; 2.1745x over previous
#include <cuda_runtime.h>
#include <cuda_bf16.h>
#include <cstdint>

// ---------------------------------------------------------------------------
// EBTAttention R3: mma.sync (HMMA m16n8k16 bf16) with bf16 hi/lo x3 split.
// tcgen05 is unavailable under this toolchain's plain sm_103 PTX target.
// ---------------------------------------------------------------------------

#define BATCH 2
#define SEQ   2048
#define HID   2048
#define NH    16
#define NKV   16
#define HD    128
#define QKV_COLS 6144
#define ROWS  4096
#define OCOLS 2048

static __device__ __align__(16) float g_qkv[(size_t)ROWS * QKV_COLS];            // 100 MB
static __device__ __align__(16) float g_scores[(size_t)BATCH * NH * SEQ * SEQ];  // 536 MB
static __device__ __align__(16) float g_attnout[(size_t)ROWS * OCOLS];           // 33 MB
static __device__ __align__(16) float g_vt[(size_t)BATCH * NH * HD * SEQ];       // 33 MB

__device__ __forceinline__ uint32_t smem_u32(const void* p) {
    uint32_t a;
    asm("{ .reg .u64 t; cvta.to.shared.u64 t, %1; cvt.u32.u64 %0, t; }" : "=r"(a) : "l"(p));
    return a;
}

#define LDSM_X4(r0, r1, r2, r3, addr) \
    asm volatile("ldmatrix.sync.aligned.m8n8.x4.shared.b16 {%0,%1,%2,%3}, [%4];" \
                 : "=r"(r0), "=r"(r1), "=r"(r2), "=r"(r3) : "r"(addr))

#define MMA16816(d, a, b) \
    asm volatile("mma.sync.aligned.m16n8k16.row.col.f32.bf16.bf16.f32 " \
                 "{%0,%1,%2,%3}, {%4,%5,%6,%7}, {%8,%9}, {%0,%1,%2,%3};" \
                 : "+f"((d)[0]), "+f"((d)[1]), "+f"((d)[2]), "+f"((d)[3]) \
                 : "r"((a)[0]), "r"((a)[1]), "r"((a)[2]), "r"((a)[3]), \
                   "r"((b)[0]), "r"((b)[1]))

// smem tile: 128 rows x 32 bf16, padded to 40 bf16 (80 B) row stride = 10240 B
#define TSTRIDE 80
#define TBYTES  10240

// Split a float4 into bf16 hi/lo pairs, store 8B each.
__device__ __forceinline__ void split_store(float4 v, uint8_t* hi, uint8_t* lo, uint32_t off)
{
    __nv_bfloat16 h0 = __float2bfloat16_rn(v.x);
    __nv_bfloat16 h1 = __float2bfloat16_rn(v.y);
    __nv_bfloat16 h2 = __float2bfloat16_rn(v.z);
    __nv_bfloat16 h3 = __float2bfloat16_rn(v.w);
    __nv_bfloat16 l0 = __float2bfloat16_rn(v.x - __bfloat162float(h0));
    __nv_bfloat16 l1 = __float2bfloat16_rn(v.y - __bfloat162float(h1));
    __nv_bfloat16 l2 = __float2bfloat16_rn(v.z - __bfloat162float(h2));
    __nv_bfloat16 l3 = __float2bfloat16_rn(v.w - __bfloat162float(h3));
    uint2 uh, ul;
    uh.x = ((uint32_t)__bfloat16_as_ushort(h1) << 16) | __bfloat16_as_ushort(h0);
    uh.y = ((uint32_t)__bfloat16_as_ushort(h3) << 16) | __bfloat16_as_ushort(h2);
    ul.x = ((uint32_t)__bfloat16_as_ushort(l1) << 16) | __bfloat16_as_ushort(l0);
    ul.y = ((uint32_t)__bfloat16_as_ushort(l3) << 16) | __bfloat16_as_ushort(l2);
    *(uint2*)(hi + off) = uh;
    *(uint2*)(lo + off) = ul;
}

// ---------------------------------------------------------------------------
// GEMM NT: C[128x128 tile] = alpha * A @ B^T. A:[M,K] lda, B:[N,K] ldb, fp32.
// K multiple of 32. 256 threads, 8 warps in 4(m) x 2(n), warp tile 32x64.
// ---------------------------------------------------------------------------
__device__ __forceinline__ void gemm_bf16x3_nt(
    const float* __restrict__ A, const float* __restrict__ B, float* __restrict__ C,
    int K, int lda, int ldb, int ldc, float alpha)
{
    __shared__ __align__(16) uint8_t sm[4 * TBYTES];
    uint8_t* Ahi = sm;
    uint8_t* Alo = sm + TBYTES;
    uint8_t* Bhi = sm + 2 * TBYTES;
    uint8_t* Blo = sm + 3 * TBYTES;

    const int tid  = threadIdx.x;
    const int wid  = tid >> 5;
    const int lane = tid & 31;
    const int warp_m = wid >> 1;   // 0..3
    const int warp_n = wid & 1;    // 0..1
    const int mrow0 = blockIdx.y * 128;
    const int ncol0 = blockIdx.x * 128;

    float acc[2][8][4];
#pragma unroll
    for (int mf = 0; mf < 2; mf++)
#pragma unroll
        for (int nf = 0; nf < 8; nf++)
#pragma unroll
            for (int j = 0; j < 4; j++) acc[mf][nf][j] = 0.0f;

    // ldmatrix lane addresses
    const uint32_t a_off = (uint32_t)(warp_m * 32 + (lane & 15)) * TSTRIDE + ((lane >> 4) * 16);
    const uint32_t b_off = (uint32_t)(warp_n * 64 + ((lane >> 4) & 1) * 8 + (lane & 7)) * TSTRIDE
                         + (((lane >> 3) & 1) * 16);
    const uint32_t sAhi = smem_u32(Ahi) + a_off;
    const uint32_t sAlo = smem_u32(Alo) + a_off;
    const uint32_t sBhi = smem_u32(Bhi) + b_off;
    const uint32_t sBlo = smem_u32(Blo) + b_off;

    // global load mapping: thread -> (rows r0 + i*32, cols c4*4..+3 within chunk)
    const int r0 = tid >> 3;
    const int c4 = tid & 7;
    const float* Ag = A + (size_t)(mrow0 + r0) * lda + (c4 << 2);
    const float* Bg = B + (size_t)(ncol0 + r0) * ldb + (c4 << 2);
    const uint32_t soff0 = (uint32_t)r0 * TSTRIDE + c4 * 8;

    const int nCh = K >> 5;

    // preload chunk 0
    {
#pragma unroll
        for (int i = 0; i < 4; i++) {
            float4 a = *(const float4*)(Ag + (size_t)i * 32 * lda);
            float4 b = *(const float4*)(Bg + (size_t)i * 32 * ldb);
            uint32_t o = soff0 + i * 32 * TSTRIDE;
            split_store(a, Ahi, Alo, o);
            split_store(b, Bhi, Blo, o);
        }
    }
    __syncthreads();

    for (int c = 0; c < nCh; c++) {
        float4 pa[4], pb[4];
        const bool more = (c + 1 < nCh);
        if (more) {
            const int kn = (c + 1) << 5;
#pragma unroll
            for (int i = 0; i < 4; i++) {
                pa[i] = *(const float4*)(Ag + (size_t)i * 32 * lda + kn);
                pb[i] = *(const float4*)(Bg + (size_t)i * 32 * ldb + kn);
            }
        }

#pragma unroll
        for (int kk = 0; kk < 2; kk++) {
            const uint32_t ko = kk * 32;  // 16 bf16 = 32 bytes
            uint32_t ah[2][4], al[2][4], bh[8][2], bl[8][2];
#pragma unroll
            for (int mf = 0; mf < 2; mf++) {
                LDSM_X4(ah[mf][0], ah[mf][1], ah[mf][2], ah[mf][3],
                        sAhi + mf * 16 * TSTRIDE + ko);
                LDSM_X4(al[mf][0], al[mf][1], al[mf][2], al[mf][3],
                        sAlo + mf * 16 * TSTRIDE + ko);
            }
#pragma unroll
            for (int p = 0; p < 4; p++) {
                LDSM_X4(bh[2*p][0], bh[2*p][1], bh[2*p+1][0], bh[2*p+1][1],
                        sBhi + p * 16 * TSTRIDE + ko);
                LDSM_X4(bl[2*p][0], bl[2*p][1], bl[2*p+1][0], bl[2*p+1][1],
                        sBlo + p * 16 * TSTRIDE + ko);
            }
#pragma unroll
            for (int mf = 0; mf < 2; mf++)
#pragma unroll
                for (int nf = 0; nf < 8; nf++) {
                    MMA16816(acc[mf][nf], ah[mf], bh[nf]);
                    MMA16816(acc[mf][nf], ah[mf], bl[nf]);
                    MMA16816(acc[mf][nf], al[mf], bh[nf]);
                }
        }
        __syncthreads();
        if (more) {
#pragma unroll
            for (int i = 0; i < 4; i++) {
                uint32_t o = soff0 + i * 32 * TSTRIDE;
                split_store(pa[i], Ahi, Alo, o);
                split_store(pb[i], Bhi, Blo, o);
            }
        }
        __syncthreads();
    }

    // epilogue
    const int crow = mrow0 + warp_m * 32 + (lane >> 2);
    const int ccol = ncol0 + warp_n * 64 + (lane & 3) * 2;
#pragma unroll
    for (int mf = 0; mf < 2; mf++)
#pragma unroll
        for (int nf = 0; nf < 8; nf++) {
            float2 v0, v1;
            v0.x = acc[mf][nf][0] * alpha; v0.y = acc[mf][nf][1] * alpha;
            v1.x = acc[mf][nf][2] * alpha; v1.y = acc[mf][nf][3] * alpha;
            *(float2*)(C + (size_t)(crow + mf * 16)     * ldc + ccol + nf * 8) = v0;
            *(float2*)(C + (size_t)(crow + mf * 16 + 8) * ldc + ccol + nf * 8) = v1;
        }
}

// ---------------------------------------------------------------------------
// Kernels
// ---------------------------------------------------------------------------
__global__ void __launch_bounds__(256) k_qkv(const float* __restrict__ hidden,
                                             const float* __restrict__ wqkv)
{
    gemm_bf16x3_nt(hidden, wqkv, g_qkv, HID, HID, HID, QKV_COLS, 1.0f);
}

__global__ void __launch_bounds__(256) k_rope(const float* __restrict__ cosp,
                                              const float* __restrict__ sinp)
{
    int idx = blockIdx.x * blockDim.x + threadIdx.x; // ROWS*32*64
    int d    = idx & 63;
    int head = (idx >> 6) & 31;
    int row  = idx >> 11;
    int s    = row & (SEQ - 1);

    float* p = g_qkv + (size_t)row * QKV_COLS + head * HD;
    float x1 = p[d];
    float x2 = p[d + 64];
    float c1 = cosp[s * HD + d],      s1 = sinp[s * HD + d];
    float c2 = cosp[s * HD + d + 64], s2 = sinp[s * HD + d + 64];
    p[d]      = x1 * c1 - x2 * s1;
    p[d + 64] = x2 * c2 + x1 * s2;
}

__global__ void __launch_bounds__(256) k_scores()
{
    int z = blockIdx.z;
    int b = z >> 4;
    int h = z & 15;
    const float* bse = g_qkv + (size_t)b * SEQ * QKV_COLS;
    gemm_bf16x3_nt(bse + h * HD, bse + (NH + h) * HD,
                   g_scores + (size_t)z * SEQ * SEQ,
                   HD, QKV_COLS, QKV_COLS, SEQ, 0.08838834764831845f);
}

// Single-pass softmax: row of 2048 cached in 8 regs/thread (256 threads).
__global__ void __launch_bounds__(256) k_softmax()
{
    float* p = g_scores + (size_t)blockIdx.x * SEQ;
    const int t = threadIdx.x;
    __shared__ float red[8];

    float4 v0 = *(float4*)(p + t * 8);
    float4 v1 = *(float4*)(p + t * 8 + 4);

    float m = fmaxf(fmaxf(fmaxf(v0.x, v0.y), fmaxf(v0.z, v0.w)),
                    fmaxf(fmaxf(v1.x, v1.y), fmaxf(v1.z, v1.w)));
#pragma unroll
    for (int o = 16; o; o >>= 1) m = fmaxf(m, __shfl_xor_sync(0xffffffffu, m, o));
    if ((t & 31) == 0) red[t >> 5] = m;
    __syncthreads();
    if (t < 32) {
        float v = (t < 8) ? red[t] : -1e30f;
#pragma unroll
        for (int o = 4; o; o >>= 1) v = fmaxf(v, __shfl_xor_sync(0xffffffffu, v, o));
        if (t == 0) red[0] = v;
    }
    __syncthreads();
    m = red[0];
    __syncthreads();

    v0.x = __expf(v0.x - m); v0.y = __expf(v0.y - m);
    v0.z = __expf(v0.z - m); v0.w = __expf(v0.w - m);
    v1.x = __expf(v1.x - m); v1.y = __expf(v1.y - m);
    v1.z = __expf(v1.z - m); v1.w = __expf(v1.w - m);
    float sum = v0.x + v0.y + v0.z + v0.w + v1.x + v1.y + v1.z + v1.w;
#pragma unroll
    for (int o = 16; o; o >>= 1) sum += __shfl_xor_sync(0xffffffffu, sum, o);
    if ((t & 31) == 0) red[t >> 5] = sum;
    __syncthreads();
    if (t < 32) {
        float v = (t < 8) ? red[t] : 0.0f;
#pragma unroll
        for (int o = 4; o; o >>= 1) v += __shfl_xor_sync(0xffffffffu, v, o);
        if (t == 0) red[0] = v;
    }
    __syncthreads();
    const float inv = 1.0f / red[0];

    v0.x *= inv; v0.y *= inv; v0.z *= inv; v0.w *= inv;
    v1.x *= inv; v1.y *= inv; v1.z *= inv; v1.w *= inv;
    *(float4*)(p + t * 8) = v0;
    *(float4*)(p + t * 8 + 4) = v1;
}

// Transpose V into g_vt[z][d][j] (K-major for the PV NT GEMM).
__global__ void __launch_bounds__(256) k_vt()
{
    __shared__ float tile[32][33];
    const int z = blockIdx.z;
    const int b = z >> 4;
    const int h = z & 15;
    const float* src = g_qkv + (size_t)b * SEQ * QKV_COLS + (NH + NKV + h) * HD;
    const int j0 = blockIdx.x * 32;
    const int d0 = blockIdx.y * 32;
    const int tx = threadIdx.x & 31;
    const int ty = threadIdx.x >> 5; // 0..7

    for (int r = ty; r < 32; r += 8)
        tile[r][tx] = src[(size_t)(j0 + r) * QKV_COLS + d0 + tx];
    __syncthreads();
    float* dst = g_vt + (size_t)z * HD * SEQ;
    for (int r = ty; r < 32; r += 8)
        dst[(size_t)(d0 + r) * SEQ + j0 + tx] = tile[tx][r];
}

__global__ void __launch_bounds__(256) k_pv()
{
    int z = blockIdx.z;
    int b = z >> 4;
    int h = z & 15;
    gemm_bf16x3_nt(g_scores + (size_t)z * SEQ * SEQ,
                   g_vt + (size_t)z * HD * SEQ,
                   g_attnout + (size_t)b * SEQ * OCOLS + h * HD,
                   SEQ, SEQ, SEQ, OCOLS, 1.0f);
}

__global__ void __launch_bounds__(256) k_oproj(const float* __restrict__ wo,
                                               float* __restrict__ out)
{
    gemm_bf16x3_nt(g_attnout, wo, out, OCOLS, OCOLS, OCOLS, HID, 1.0f);
}

// ---------------------------------------------------------------------------
// Launch
// ---------------------------------------------------------------------------
extern "C" void kernel_launch(void* const* d_in, const int* in_sizes, int n_in,
                              void* d_out, int out_size)
{
    const float* hidden = (const float*)d_in[0];
    const float* cosp   = (const float*)d_in[1];
    const float* sinp   = (const float*)d_in[2];
    const float* wqkv   = (const float*)d_in[3];
    const float* wo     = (const float*)d_in[4];
    float* out = (float*)d_out;

    k_qkv<<<dim3(QKV_COLS / 128, ROWS / 128), 256>>>(hidden, wqkv);
    k_rope<<<(ROWS * 32 * 64) / 256, 256>>>(cosp, sinp);
    k_vt<<<dim3(SEQ / 32, HD / 32, BATCH * NH), 256>>>();
    k_scores<<<dim3(SEQ / 128, SEQ / 128, BATCH * NH), 256>>>();
    k_softmax<<<BATCH * NH * SEQ, 256>>>();
    k_pv<<<dim3(1, SEQ / 128, BATCH * NH), 256>>>();
    k_oproj<<<dim3(OCOLS / 128, ROWS / 128), 256>>>(wo, out);
}

// round 5
// speedup vs baseline: 2.6511x; 1.2192x over previous
#include <cuda_runtime.h>
#include <cuda_bf16.h>
#include <cstdint>

// ---------------------------------------------------------------------------
// EBTAttention R4: presplit bf16 hi/lo + cp.async double-buffered HMMA GEMMs
//                  + flash-fused attention (no scores materialization).
// ---------------------------------------------------------------------------

#define BATCH 2
#define SEQ   2048
#define HID   2048
#define NH    16
#define HD    128
#define QKV_COLS 6144
#define ROWS  4096
#define NZ    32              // BATCH * NH

typedef unsigned short u16;

// fp32 scratch
static __device__ __align__(16) float g_qkv[(size_t)ROWS * QKV_COLS];       // 100 MB
// presplit bf16 buffers
static __device__ __align__(16) u16 g_h_hi[(size_t)ROWS * HID];
static __device__ __align__(16) u16 g_h_lo[(size_t)ROWS * HID];
static __device__ __align__(16) u16 g_wqkv_hi[(size_t)QKV_COLS * HID];
static __device__ __align__(16) u16 g_wqkv_lo[(size_t)QKV_COLS * HID];
static __device__ __align__(16) u16 g_wo_hi[(size_t)HID * HID];
static __device__ __align__(16) u16 g_wo_lo[(size_t)HID * HID];
static __device__ __align__(16) u16 g_q_hi[(size_t)NZ * SEQ * HD];
static __device__ __align__(16) u16 g_q_lo[(size_t)NZ * SEQ * HD];
static __device__ __align__(16) u16 g_k_hi[(size_t)NZ * SEQ * HD];
static __device__ __align__(16) u16 g_k_lo[(size_t)NZ * SEQ * HD];
static __device__ __align__(16) u16 g_v_hi[(size_t)NZ * SEQ * HD];
static __device__ __align__(16) u16 g_v_lo[(size_t)NZ * SEQ * HD];
static __device__ __align__(16) u16 g_ao_hi[(size_t)ROWS * HID];
static __device__ __align__(16) u16 g_ao_lo[(size_t)ROWS * HID];

#define QSCALE 0.12751882456102142f   // (1/sqrt(128)) * log2(e)

__device__ __forceinline__ uint32_t smem_u32(const void* p) {
    uint32_t a;
    asm("{ .reg .u64 t; cvta.to.shared.u64 t, %1; cvt.u32.u64 %0, t; }" : "=r"(a) : "l"(p));
    return a;
}

#define LDSM_X4(r0, r1, r2, r3, addr) \
    asm volatile("ldmatrix.sync.aligned.m8n8.x4.shared.b16 {%0,%1,%2,%3}, [%4];" \
                 : "=r"(r0), "=r"(r1), "=r"(r2), "=r"(r3) : "r"(addr))
#define LDSM_X4_T(r0, r1, r2, r3, addr) \
    asm volatile("ldmatrix.sync.aligned.m8n8.x4.trans.shared.b16 {%0,%1,%2,%3}, [%4];" \
                 : "=r"(r0), "=r"(r1), "=r"(r2), "=r"(r3) : "r"(addr))

#define MMA16816(d, a, b0, b1) \
    asm volatile("mma.sync.aligned.m16n8k16.row.col.f32.bf16.bf16.f32 " \
                 "{%0,%1,%2,%3}, {%4,%5,%6,%7}, {%8,%9}, {%0,%1,%2,%3};" \
                 : "+f"((d)[0]), "+f"((d)[1]), "+f"((d)[2]), "+f"((d)[3]) \
                 : "r"((a)[0]), "r"((a)[1]), "r"((a)[2]), "r"((a)[3]), \
                   "r"(b0), "r"(b1))

#define CP_ASYNC16(s, g) \
    asm volatile("cp.async.ca.shared.global [%0], [%1], 16;" :: "r"(s), "l"(g))
#define CP_COMMIT() asm volatile("cp.async.commit_group;" ::: "memory")
#define CP_WAIT1()  asm volatile("cp.async.wait_group 1;" ::: "memory")
#define CP_WAIT0()  asm volatile("cp.async.wait_group 0;" ::: "memory")

__device__ __forceinline__ uint32_t packbf(__nv_bfloat16 a, __nv_bfloat16 b) {
    return ((uint32_t)__bfloat16_as_ushort(b) << 16) | __bfloat16_as_ushort(a);
}
__device__ __forceinline__ void split2(float x, float y, uint32_t& hi, uint32_t& lo) {
    __nv_bfloat16 hx = __float2bfloat16_rn(x);
    __nv_bfloat16 hy = __float2bfloat16_rn(y);
    hi = packbf(hx, hy);
    lo = packbf(__float2bfloat16_rn(x - __bfloat162float(hx)),
                __float2bfloat16_rn(y - __bfloat162float(hy)));
}

// ---------------------------------------------------------------------------
// Generic fp32 -> bf16 hi/lo split (4 elems/thread)
// ---------------------------------------------------------------------------
__global__ void __launch_bounds__(256) k_split(const float* __restrict__ src,
                                               u16* __restrict__ hi, u16* __restrict__ lo)
{
    size_t i = ((size_t)blockIdx.x * 256 + threadIdx.x) * 4;
    float4 v = *(const float4*)(src + i);
    uint32_t h0, l0, h1, l1;
    split2(v.x, v.y, h0, l0);
    split2(v.z, v.w, h1, l1);
    uint2 uh = {h0, h1}, ul = {l0, l1};
    *(uint2*)(hi + i) = uh;
    *(uint2*)(lo + i) = ul;
}

// ---------------------------------------------------------------------------
// GEMM v2: C[M,N] = A @ B^T in bf16x3 via phase-interleaved K'=3K pipeline.
// A,B presplit bf16 [rows, 2048]. Tile 128x128, BK=32, 256 thr, cp.async x2 buf.
// ---------------------------------------------------------------------------
#define GK 2048
#define NSTAGE 192   // 3 * (2048/32)

__device__ __forceinline__ void gemm_v2(
    const u16* __restrict__ Ah, const u16* __restrict__ Al,
    const u16* __restrict__ Bh, const u16* __restrict__ Bl,
    float* __restrict__ C, int ldc)
{
    __shared__ __align__(16) unsigned char smbuf[4][10240]; // A0,B0,A1,B1

    const int tid = threadIdx.x, lane = tid & 31, wid = tid >> 5;
    const int wm = wid >> 1, wn = wid & 1;
    const int m0 = blockIdx.y * 128, n0 = blockIdx.x * 128;

    float acc[2][8][4] = {};

    const uint32_t smA0 = smem_u32(smbuf[0]);
    const uint32_t smB0 = smem_u32(smbuf[1]);
    const uint32_t smA1 = smem_u32(smbuf[2]);
    const uint32_t smB1 = smem_u32(smbuf[3]);

    const int lr = tid >> 2;       // 0..63
    const int lq = tid & 3;
    const uint32_t st0 = (uint32_t)lr * 80 + lq * 16;
    const uint32_t st1 = (uint32_t)(lr + 64) * 80 + lq * 16;

    const uint32_t a_off = (uint32_t)(wm * 32 + (lane & 15)) * 80 + ((lane >> 4) * 16);
    const uint32_t b_off = (uint32_t)(wn * 64 + ((lane >> 4) & 1) * 8 + (lane & 7)) * 80
                         + (((lane >> 3) & 1) * 16);

    const u16* Asel[3] = {Ah, Ah, Al};
    const u16* Bsel[3] = {Bh, Bl, Bh};

#define LOAD_STAGE(s, buf) do { \
        const int ph = (s) % 3; \
        const int k0 = ((s) / 3) * 32; \
        const u16* Ag = Asel[ph] + (size_t)(m0 + lr) * GK + k0 + lq * 8; \
        const u16* Bg = Bsel[ph] + (size_t)(n0 + lr) * GK + k0 + lq * 8; \
        uint32_t dA = (buf) ? smA1 : smA0, dB = (buf) ? smB1 : smB0; \
        CP_ASYNC16(dA + st0, Ag); \
        CP_ASYNC16(dA + st1, Ag + (size_t)64 * GK); \
        CP_ASYNC16(dB + st0, Bg); \
        CP_ASYNC16(dB + st1, Bg + (size_t)64 * GK); \
    } while (0)

    LOAD_STAGE(0, 0);
    CP_COMMIT();

    for (int s = 0; s < NSTAGE; s++) {
        if (s + 1 < NSTAGE) LOAD_STAGE(s + 1, (s + 1) & 1);
        CP_COMMIT();
        if (s + 1 < NSTAGE) { CP_WAIT1(); } else { CP_WAIT0(); }
        __syncthreads();

        const uint32_t sa = ((s & 1) ? smA1 : smA0) + a_off;
        const uint32_t sb = ((s & 1) ? smB1 : smB0) + b_off;
#pragma unroll
        for (int c = 0; c < 2; c++) {
            uint32_t af[2][4], bf[8][2];
#pragma unroll
            for (int mf = 0; mf < 2; mf++)
                LDSM_X4(af[mf][0], af[mf][1], af[mf][2], af[mf][3],
                        sa + mf * 16 * 80 + c * 32);
#pragma unroll
            for (int p = 0; p < 4; p++)
                LDSM_X4(bf[2*p][0], bf[2*p][1], bf[2*p+1][0], bf[2*p+1][1],
                        sb + p * 16 * 80 + c * 32);
#pragma unroll
            for (int mf = 0; mf < 2; mf++)
#pragma unroll
                for (int nf = 0; nf < 8; nf++)
                    MMA16816(acc[mf][nf], af[mf], bf[nf][0], bf[nf][1]);
        }
        __syncthreads();
    }
#undef LOAD_STAGE

    const int crow = m0 + wm * 32 + (lane >> 2);
    const int ccol = n0 + wn * 64 + (lane & 3) * 2;
#pragma unroll
    for (int mf = 0; mf < 2; mf++)
#pragma unroll
        for (int nf = 0; nf < 8; nf++) {
            float2 v0 = {acc[mf][nf][0], acc[mf][nf][1]};
            float2 v1 = {acc[mf][nf][2], acc[mf][nf][3]};
            *(float2*)(C + (size_t)(crow + mf * 16)     * ldc + ccol + nf * 8) = v0;
            *(float2*)(C + (size_t)(crow + mf * 16 + 8) * ldc + ccol + nf * 8) = v1;
        }
}

__global__ void __launch_bounds__(256) k_qkv()
{
    gemm_v2(g_h_hi, g_h_lo, g_wqkv_hi, g_wqkv_lo, g_qkv, QKV_COLS);
}

__global__ void __launch_bounds__(256) k_oproj(float* __restrict__ out)
{
    gemm_v2(g_ao_hi, g_ao_lo, g_wo_hi, g_wo_lo, out, HID);
}

// ---------------------------------------------------------------------------
// RoPE + split + repack into per-head-contiguous q/k/v (q folded with scale).
// grid (1024, 48), 256 thr: block.x covers 4 rows, block.y = head 0..47.
// ---------------------------------------------------------------------------
__global__ void __launch_bounds__(256) k_rope_split(const float* __restrict__ cosp,
                                                    const float* __restrict__ sinp)
{
    const int d = threadIdx.x & 63;
    const int row = blockIdx.x * 4 + (threadIdx.x >> 6);
    const int head = blockIdx.y;         // 0..47
    const int s = row & (SEQ - 1);
    const int b = row >> 11;

    const float* p = g_qkv + (size_t)row * QKV_COLS + head * HD;
    float x1 = p[d];
    float x2 = p[d + 64];
    float y1, y2;
    if (head < 32) {
        float c1 = cosp[s * HD + d],      s1 = sinp[s * HD + d];
        float c2 = cosp[s * HD + d + 64], s2 = sinp[s * HD + d + 64];
        y1 = x1 * c1 - x2 * s1;
        y2 = x2 * c2 + x1 * s2;
    } else { y1 = x1; y2 = x2; }

    u16 *dh, *dl;
    int h;
    if (head < 16)      { h = head;      dh = g_q_hi; dl = g_q_lo; y1 *= QSCALE; y2 *= QSCALE; }
    else if (head < 32) { h = head - 16; dh = g_k_hi; dl = g_k_lo; }
    else                { h = head - 32; dh = g_v_hi; dl = g_v_lo; }

    const size_t base = ((size_t)(b * NH + h) * SEQ + s) * HD;
    __nv_bfloat16 h1 = __float2bfloat16_rn(y1);
    __nv_bfloat16 h2 = __float2bfloat16_rn(y2);
    dh[base + d]      = __bfloat16_as_ushort(h1);
    dh[base + d + 64] = __bfloat16_as_ushort(h2);
    dl[base + d]      = __bfloat16_as_ushort(__float2bfloat16_rn(y1 - __bfloat162float(h1)));
    dl[base + d + 64] = __bfloat16_as_ushort(__float2bfloat16_rn(y2 - __bfloat162float(h2)));
}

// ---------------------------------------------------------------------------
// Flash attention: grid (16 qblocks, 32 z), 256 thr (8 warps x 16 Q rows).
// KV tiles of 64, double-buffered cp.async. bf16x3 for S and PV.
// smem: Qh(34816) Ql(34816) | 2 x [Kh Kl Vh Vl](17408 each) = 208896 B.
// ---------------------------------------------------------------------------
#define FSTR 272          // smem row stride bytes (128 bf16 + pad)
#define QTILE 34816       // 128*272
#define KVT   17408       // 64*272
#define KVBUF 69632       // 4*17408
#define FSMEM 208896

__global__ void __launch_bounds__(256, 1) k_flash()
{
    extern __shared__ __align__(16) unsigned char dsm[];
    const int tid = threadIdx.x, lane = tid & 31, w = tid >> 5;
    const int qb = blockIdx.x, z = blockIdx.y;
    const int b = z >> 4, h = z & 15;

    const uint32_t smQh = smem_u32(dsm);
    const uint32_t smQl = smQh + QTILE;
    const uint32_t smKV = smQh + 2 * QTILE;

    const size_t zbase = (size_t)z * SEQ * HD;
    const u16* gqh = g_q_hi + zbase + (size_t)qb * 128 * HD;
    const u16* gql = g_q_lo + zbase + (size_t)qb * 128 * HD;
    const u16* gkh = g_k_hi + zbase;
    const u16* gkl = g_k_lo + zbase;
    const u16* gvh = g_v_hi + zbase;
    const u16* gvl = g_v_lo + zbase;

    // ---- Q load (once): 128 rows x 256B, 16 chunks/row -> 8 per thread/half
    {
        const int ch0 = tid;   // chunks ch0 + i*256
#pragma unroll
        for (int i = 0; i < 8; i++) {
            int ch = i * 256 + ch0;
            int r = ch >> 4, q = ch & 15;
            CP_ASYNC16(smQh + r * FSTR + q * 16, gqh + r * HD + q * 8);
            CP_ASYNC16(smQl + r * FSTR + q * 16, gql + r * HD + q * 8);
        }
    }
    // ---- KV tile loader: 64 rows x 256B per array -> 4 chunks/thread/array
#define LOAD_KV(t, buf) do { \
        uint32_t kb = smKV + (buf) * KVBUF; \
        const size_t rb = (size_t)(t) * 64; \
        _Pragma("unroll") \
        for (int i = 0; i < 4; i++) { \
            int ch = i * 256 + tid; \
            int r = ch >> 4, q = ch & 15; \
            uint32_t so = r * FSTR + q * 16; \
            size_t go = (rb + r) * HD + q * 8; \
            CP_ASYNC16(kb + so,            gkh + go); \
            CP_ASYNC16(kb + KVT + so,      gkl + go); \
            CP_ASYNC16(kb + 2 * KVT + so,  gvh + go); \
            CP_ASYNC16(kb + 3 * KVT + so,  gvl + go); \
        } \
    } while (0)

    LOAD_KV(0, 0);
    CP_COMMIT();

    // per-thread ldmatrix offsets
    const uint32_t a_off = (uint32_t)(w * 16 + (lane & 15)) * FSTR + ((lane >> 4) * 16);
    const uint32_t kb_off = (uint32_t)(((lane >> 4) & 1) * 8 + (lane & 7)) * FSTR
                          + (((lane >> 3) & 1) * 16);
    const uint32_t v_off = (uint32_t)(((lane >> 3) & 1) * 8 + (lane & 7)) * FSTR
                         + (((lane >> 4) & 1) * 16);

    float o[16][4] = {};
    float m0 = -1e30f, m1 = -1e30f, l0 = 0.0f, l1 = 0.0f;

    for (int t = 0; t < 32; t++) {
        if (t + 1 < 32) LOAD_KV(t + 1, (t + 1) & 1);
        CP_COMMIT();
        if (t + 1 < 32) { CP_WAIT1(); } else { CP_WAIT0(); }
        __syncthreads();

        const uint32_t kb = smKV + (t & 1) * KVBUF;
        const uint32_t sKh = kb + kb_off;
        const uint32_t sKl = kb + KVT + kb_off;
        const uint32_t sVh = kb + 2 * KVT + v_off;
        const uint32_t sVl = kb + 3 * KVT + v_off;
        const uint32_t sQh = smQh + a_off;
        const uint32_t sQl = smQl + a_off;

        // ---- S = Qhat . K^T  (bf16x3), warp: 16 rows x 64 kv
        float sf[8][4] = {};
#pragma unroll
        for (int c = 0; c < 8; c++) {
            uint32_t qh[4], ql[4];
            LDSM_X4(qh[0], qh[1], qh[2], qh[3], sQh + c * 32);
            LDSM_X4(ql[0], ql[1], ql[2], ql[3], sQl + c * 32);
#pragma unroll
            for (int p = 0; p < 4; p++) {
                uint32_t kh[4], kl[4];
                LDSM_X4(kh[0], kh[1], kh[2], kh[3], sKh + p * 16 * FSTR + c * 32);
                LDSM_X4(kl[0], kl[1], kl[2], kl[3], sKl + p * 16 * FSTR + c * 32);
                MMA16816(sf[2*p],   qh, kh[0], kh[1]);
                MMA16816(sf[2*p],   qh, kl[0], kl[1]);
                MMA16816(sf[2*p],   ql, kh[0], kh[1]);
                MMA16816(sf[2*p+1], qh, kh[2], kh[3]);
                MMA16816(sf[2*p+1], qh, kl[2], kl[3]);
                MMA16816(sf[2*p+1], ql, kh[2], kh[3]);
            }
        }

        // ---- online softmax (s already in log2 units)
        float tm0 = -1e30f, tm1 = -1e30f;
#pragma unroll
        for (int e = 0; e < 8; e++) {
            tm0 = fmaxf(tm0, fmaxf(sf[e][0], sf[e][1]));
            tm1 = fmaxf(tm1, fmaxf(sf[e][2], sf[e][3]));
        }
        tm0 = fmaxf(tm0, __shfl_xor_sync(0xffffffffu, tm0, 1));
        tm0 = fmaxf(tm0, __shfl_xor_sync(0xffffffffu, tm0, 2));
        tm1 = fmaxf(tm1, __shfl_xor_sync(0xffffffffu, tm1, 1));
        tm1 = fmaxf(tm1, __shfl_xor_sync(0xffffffffu, tm1, 2));
        const float m0n = fmaxf(m0, tm0), m1n = fmaxf(m1, tm1);
        const float c0 = exp2f(m0 - m0n), c1 = exp2f(m1 - m1n);
        float ts0 = 0.0f, ts1 = 0.0f;
#pragma unroll
        for (int e = 0; e < 8; e++) {
            sf[e][0] = exp2f(sf[e][0] - m0n);
            sf[e][1] = exp2f(sf[e][1] - m0n);
            sf[e][2] = exp2f(sf[e][2] - m1n);
            sf[e][3] = exp2f(sf[e][3] - m1n);
            ts0 += sf[e][0] + sf[e][1];
            ts1 += sf[e][2] + sf[e][3];
        }
        ts0 += __shfl_xor_sync(0xffffffffu, ts0, 1);
        ts0 += __shfl_xor_sync(0xffffffffu, ts0, 2);
        ts1 += __shfl_xor_sync(0xffffffffu, ts1, 1);
        ts1 += __shfl_xor_sync(0xffffffffu, ts1, 2);
        l0 = l0 * c0 + ts0;
        l1 = l1 * c1 + ts1;
        m0 = m0n; m1 = m1n;
#pragma unroll
        for (int f = 0; f < 16; f++) {
            o[f][0] *= c0; o[f][1] *= c0;
            o[f][2] *= c1; o[f][3] *= c1;
        }

        // ---- O += P . V  (bf16x3)
#pragma unroll
        for (int j = 0; j < 4; j++) {
            uint32_t ah[4], al[4];
            split2(sf[2*j][0],   sf[2*j][1],   ah[0], al[0]);
            split2(sf[2*j][2],   sf[2*j][3],   ah[1], al[1]);
            split2(sf[2*j+1][0], sf[2*j+1][1], ah[2], al[2]);
            split2(sf[2*j+1][2], sf[2*j+1][3], ah[3], al[3]);
#pragma unroll
            for (int f = 0; f < 8; f++) {
                uint32_t vh[4], vl[4];
                LDSM_X4_T(vh[0], vh[1], vh[2], vh[3], sVh + j * 16 * FSTR + f * 32);
                LDSM_X4_T(vl[0], vl[1], vl[2], vl[3], sVl + j * 16 * FSTR + f * 32);
                MMA16816(o[2*f],   ah, vh[0], vh[1]);
                MMA16816(o[2*f],   ah, vl[0], vl[1]);
                MMA16816(o[2*f],   al, vh[0], vh[1]);
                MMA16816(o[2*f+1], ah, vh[2], vh[3]);
                MMA16816(o[2*f+1], ah, vl[2], vl[3]);
                MMA16816(o[2*f+1], al, vh[2], vh[3]);
            }
        }
        __syncthreads();
    }
#undef LOAD_KV

    // ---- epilogue: normalize, split, store to g_ao
    const float inv0 = 1.0f / l0, inv1 = 1.0f / l1;
    const size_t row0 = (size_t)(b * SEQ + qb * 128 + w * 16 + (lane >> 2));
    const size_t colb = (size_t)h * HD + (lane & 3) * 2;
#pragma unroll
    for (int f = 0; f < 16; f++) {
        uint32_t h01, l01, h23, l23;
        split2(o[f][0] * inv0, o[f][1] * inv0, h01, l01);
        split2(o[f][2] * inv1, o[f][3] * inv1, h23, l23);
        size_t i0 = row0 * HID + colb + f * 8;
        size_t i1 = i0 + (size_t)8 * HID;
        *(uint32_t*)(g_ao_hi + i0) = h01;
        *(uint32_t*)(g_ao_lo + i0) = l01;
        *(uint32_t*)(g_ao_hi + i1) = h23;
        *(uint32_t*)(g_ao_lo + i1) = l23;
    }
}

// ---------------------------------------------------------------------------
// Launch
// ---------------------------------------------------------------------------
extern "C" void kernel_launch(void* const* d_in, const int* in_sizes, int n_in,
                              void* d_out, int out_size)
{
    const float* hidden = (const float*)d_in[0];
    const float* cosp   = (const float*)d_in[1];
    const float* sinp   = (const float*)d_in[2];
    const float* wqkv   = (const float*)d_in[3];
    const float* wo     = (const float*)d_in[4];
    float* out = (float*)d_out;

    cudaFuncSetAttribute(k_flash, cudaFuncAttributeMaxDynamicSharedMemorySize, FSMEM);

    u16 *hh, *hl, *wh, *wl, *oh, *ol;
    cudaGetSymbolAddress((void**)&hh, g_h_hi);
    cudaGetSymbolAddress((void**)&hl, g_h_lo);
    cudaGetSymbolAddress((void**)&wh, g_wqkv_hi);
    cudaGetSymbolAddress((void**)&wl, g_wqkv_lo);
    cudaGetSymbolAddress((void**)&oh, g_wo_hi);
    cudaGetSymbolAddress((void**)&ol, g_wo_lo);

    k_split<<<(ROWS * HID) / 1024, 256>>>(hidden, hh, hl);
    k_split<<<(QKV_COLS * HID) / 1024, 256>>>(wqkv, wh, wl);
    k_split<<<(HID * HID) / 1024, 256>>>(wo, oh, ol);

    k_qkv<<<dim3(QKV_COLS / 128, ROWS / 128), 256>>>();
    k_rope_split<<<dim3(1024, 48), 256>>>(cosp, sinp);
    k_flash<<<dim3(16, 32), 256, FSMEM>>>();
    k_oproj<<<dim3(HID / 128, ROWS / 128), 256>>>(out);
}

// round 6
// speedup vs baseline: 2.9424x; 1.1099x over previous
#include <cuda_runtime.h>
#include <cuda_bf16.h>
#include <cstdint>

// ---------------------------------------------------------------------------
// EBTAttention R5: co-resident bf16x3 GEMM (1 sync/stage, 3-stage cp.async,
// XOR swizzle) + unchanged flash attention.
// ---------------------------------------------------------------------------

#define BATCH 2
#define SEQ   2048
#define HID   2048
#define NH    16
#define HD    128
#define QKV_COLS 6144
#define ROWS  4096
#define NZ    32
#define GK    2048

typedef unsigned short u16;

static __device__ __align__(16) float g_qkv[(size_t)ROWS * QKV_COLS];
static __device__ __align__(16) u16 g_h_hi[(size_t)ROWS * HID];
static __device__ __align__(16) u16 g_h_lo[(size_t)ROWS * HID];
static __device__ __align__(16) u16 g_wqkv_hi[(size_t)QKV_COLS * HID];
static __device__ __align__(16) u16 g_wqkv_lo[(size_t)QKV_COLS * HID];
static __device__ __align__(16) u16 g_wo_hi[(size_t)HID * HID];
static __device__ __align__(16) u16 g_wo_lo[(size_t)HID * HID];
static __device__ __align__(16) u16 g_q_hi[(size_t)NZ * SEQ * HD];
static __device__ __align__(16) u16 g_q_lo[(size_t)NZ * SEQ * HD];
static __device__ __align__(16) u16 g_k_hi[(size_t)NZ * SEQ * HD];
static __device__ __align__(16) u16 g_k_lo[(size_t)NZ * SEQ * HD];
static __device__ __align__(16) u16 g_v_hi[(size_t)NZ * SEQ * HD];
static __device__ __align__(16) u16 g_v_lo[(size_t)NZ * SEQ * HD];
static __device__ __align__(16) u16 g_ao_hi[(size_t)ROWS * HID];
static __device__ __align__(16) u16 g_ao_lo[(size_t)ROWS * HID];

#define QSCALE 0.12751882456102142f   // (1/sqrt(128)) * log2(e)

__device__ __forceinline__ uint32_t smem_u32(const void* p) {
    uint32_t a;
    asm("{ .reg .u64 t; cvta.to.shared.u64 t, %1; cvt.u32.u64 %0, t; }" : "=r"(a) : "l"(p));
    return a;
}

#define LDSM_X4(r0, r1, r2, r3, addr) \
    asm volatile("ldmatrix.sync.aligned.m8n8.x4.shared.b16 {%0,%1,%2,%3}, [%4];" \
                 : "=r"(r0), "=r"(r1), "=r"(r2), "=r"(r3) : "r"(addr))
#define LDSM_X4_T(r0, r1, r2, r3, addr) \
    asm volatile("ldmatrix.sync.aligned.m8n8.x4.trans.shared.b16 {%0,%1,%2,%3}, [%4];" \
                 : "=r"(r0), "=r"(r1), "=r"(r2), "=r"(r3) : "r"(addr))

#define MMA16816(d, a, b0, b1) \
    asm volatile("mma.sync.aligned.m16n8k16.row.col.f32.bf16.bf16.f32 " \
                 "{%0,%1,%2,%3}, {%4,%5,%6,%7}, {%8,%9}, {%0,%1,%2,%3};" \
                 : "+f"((d)[0]), "+f"((d)[1]), "+f"((d)[2]), "+f"((d)[3]) \
                 : "r"((a)[0]), "r"((a)[1]), "r"((a)[2]), "r"((a)[3]), \
                   "r"(b0), "r"(b1))

#define CP_ASYNC16(s, g) \
    asm volatile("cp.async.ca.shared.global [%0], [%1], 16;" :: "r"(s), "l"(g))
#define CP_COMMIT() asm volatile("cp.async.commit_group;" ::: "memory")
#define CP_WAIT1()  asm volatile("cp.async.wait_group 1;" ::: "memory")
#define CP_WAIT0()  asm volatile("cp.async.wait_group 0;" ::: "memory")

__device__ __forceinline__ uint32_t packbf(__nv_bfloat16 a, __nv_bfloat16 b) {
    return ((uint32_t)__bfloat16_as_ushort(b) << 16) | __bfloat16_as_ushort(a);
}
__device__ __forceinline__ void split2(float x, float y, uint32_t& hi, uint32_t& lo) {
    __nv_bfloat16 hx = __float2bfloat16_rn(x);
    __nv_bfloat16 hy = __float2bfloat16_rn(y);
    hi = packbf(hx, hy);
    lo = packbf(__float2bfloat16_rn(x - __bfloat162float(hx)),
                __float2bfloat16_rn(y - __bfloat162float(hy)));
}

__global__ void __launch_bounds__(256) k_split(const float* __restrict__ src,
                                               u16* __restrict__ hi, u16* __restrict__ lo)
{
    size_t i = ((size_t)blockIdx.x * 256 + threadIdx.x) * 4;
    float4 v = *(const float4*)(src + i);
    uint32_t h0, l0, h1, l1;
    split2(v.x, v.y, h0, l0);
    split2(v.z, v.w, h1, l1);
    uint2 uh = {h0, h1}, ul = {l0, l1};
    *(uint2*)(hi + i) = uh;
    *(uint2*)(lo + i) = ul;
}

// ---------------------------------------------------------------------------
// GEMM v3: co-resident Ah/Al/Bh/Bl per 32-k chunk, 3-stage cp.async pipeline,
// XOR-swizzled smem, 1 sync/stage. Tile 128x128, 256 thr, 2 CTAs/SM.
// smem layout per stage (32KB): [Ah | Al | Bh | Bl], each 8KB:
//   tile(row 0..127, chunk 0..3): addr = row*64 + ((chunk ^ ((row>>1)&3))<<4)
// ---------------------------------------------------------------------------
#define GSTAGE 32768
#define GTILE  8192
#define GSMEM  98304   // 3 stages

__device__ __forceinline__ void gemm_v3(
    const u16* __restrict__ Ah_, const u16* __restrict__ Al_,
    const u16* __restrict__ Bh_, const u16* __restrict__ Bl_,
    float* __restrict__ C, int ldc)
{
    extern __shared__ __align__(16) unsigned char gsm[];
    const uint32_t smb = smem_u32(gsm);

    const int tid = threadIdx.x, lane = tid & 31, wid = tid >> 5;
    const int wm = wid >> 1, wn = wid & 1;
    const int m0 = blockIdx.y * 128, n0 = blockIdx.x * 128;

    float acc[2][8][4] = {};

    // cp.async mapping: thread -> row tid>>1, chunk pair (tid&1)*2
    const int r = tid >> 1;
    const int cp0 = (tid & 1) * 2;
    const uint32_t xs = (uint32_t)((r >> 1) & 3);
    const uint32_t st0 = (uint32_t)r * 64 + (((uint32_t)cp0 ^ xs) << 4);
    const uint32_t st1 = (uint32_t)r * 64 + (((uint32_t)(cp0 + 1) ^ xs) << 4);
    const size_t gA0 = (size_t)(m0 + r) * GK + cp0 * 8;
    const size_t gB0 = (size_t)(n0 + r) * GK + cp0 * 8;

#define G_LOAD(kt, buf) do { \
        const uint32_t sb_ = smb + (uint32_t)(buf) * GSTAGE; \
        const size_t ga_ = gA0 + (size_t)(kt) * 32; \
        const size_t gb_ = gB0 + (size_t)(kt) * 32; \
        CP_ASYNC16(sb_ + st0, Ah_ + ga_); \
        CP_ASYNC16(sb_ + st1, Ah_ + ga_ + 8); \
        CP_ASYNC16(sb_ + GTILE + st0, Al_ + ga_); \
        CP_ASYNC16(sb_ + GTILE + st1, Al_ + ga_ + 8); \
        CP_ASYNC16(sb_ + 2 * GTILE + st0, Bh_ + gb_); \
        CP_ASYNC16(sb_ + 2 * GTILE + st1, Bh_ + gb_ + 8); \
        CP_ASYNC16(sb_ + 3 * GTILE + st0, Bl_ + gb_); \
        CP_ASYNC16(sb_ + 3 * GTILE + st1, Bl_ + gb_ + 8); \
    } while (0)

    // ldmatrix per-thread constants
    const int l15 = lane & 15;
    const int l7  = lane & 7;
    const uint32_t xrA = (uint32_t)((l15 >> 1) & 3);
    const uint32_t xrB = (uint32_t)((l7 >> 1) & 3);
    const uint32_t arow = (uint32_t)(wm * 32 + l15) * 64;
    const uint32_t brow = (uint32_t)(wn * 64 + ((lane >> 4) & 1) * 8 + l7) * 64;
    const uint32_t abit = (uint32_t)(lane >> 4);        // chunk low bit for A
    const uint32_t bbit = (uint32_t)((lane >> 3) & 1);  // chunk low bit for B
    uint32_t aswz[2], bswz[2];
#pragma unroll
    for (int ci = 0; ci < 2; ci++) {
        aswz[ci] = (((uint32_t)(2 * ci) + abit) ^ xrA) << 4;
        bswz[ci] = (((uint32_t)(2 * ci) + bbit) ^ xrB) << 4;
    }

    const int NCH = GK / 32;  // 64

    G_LOAD(0, 0); CP_COMMIT();
    G_LOAD(1, 1); CP_COMMIT();

    int buf = 0;
    for (int c = 0; c < NCH; c++) {
        CP_WAIT1();
        __syncthreads();

        if (c + 2 < NCH) {
            int nb = buf + 2; if (nb >= 3) nb -= 3;
            G_LOAD(c + 2, nb);
        }
        CP_COMMIT();

        const uint32_t sb = smb + (uint32_t)buf * GSTAGE;
#pragma unroll
        for (int ci = 0; ci < 2; ci++) {
            uint32_t ah[2][4], al[2][4];
#pragma unroll
            for (int mf = 0; mf < 2; mf++) {
                LDSM_X4(ah[mf][0], ah[mf][1], ah[mf][2], ah[mf][3],
                        sb + arow + mf * 1024 + aswz[ci]);
                LDSM_X4(al[mf][0], al[mf][1], al[mf][2], al[mf][3],
                        sb + GTILE + arow + mf * 1024 + aswz[ci]);
            }
#pragma unroll
            for (int p = 0; p < 4; p++) {
                uint32_t bh[4], bl[4];
                LDSM_X4(bh[0], bh[1], bh[2], bh[3],
                        sb + 2 * GTILE + brow + p * 1024 + bswz[ci]);
                LDSM_X4(bl[0], bl[1], bl[2], bl[3],
                        sb + 3 * GTILE + brow + p * 1024 + bswz[ci]);
#pragma unroll
                for (int mf = 0; mf < 2; mf++) {
                    MMA16816(acc[mf][2*p],   ah[mf], bh[0], bh[1]);
                    MMA16816(acc[mf][2*p],   ah[mf], bl[0], bl[1]);
                    MMA16816(acc[mf][2*p],   al[mf], bh[0], bh[1]);
                    MMA16816(acc[mf][2*p+1], ah[mf], bh[2], bh[3]);
                    MMA16816(acc[mf][2*p+1], ah[mf], bl[2], bl[3]);
                    MMA16816(acc[mf][2*p+1], al[mf], bh[2], bh[3]);
                }
            }
        }
        if (++buf == 3) buf = 0;
    }
#undef G_LOAD

    const int crow = m0 + wm * 32 + (lane >> 2);
    const int ccol = n0 + wn * 64 + (lane & 3) * 2;
#pragma unroll
    for (int mf = 0; mf < 2; mf++)
#pragma unroll
        for (int nf = 0; nf < 8; nf++) {
            float2 v0 = {acc[mf][nf][0], acc[mf][nf][1]};
            float2 v1 = {acc[mf][nf][2], acc[mf][nf][3]};
            *(float2*)(C + (size_t)(crow + mf * 16)     * ldc + ccol + nf * 8) = v0;
            *(float2*)(C + (size_t)(crow + mf * 16 + 8) * ldc + ccol + nf * 8) = v1;
        }
}

__global__ void __launch_bounds__(256, 2) k_qkv()
{
    gemm_v3(g_h_hi, g_h_lo, g_wqkv_hi, g_wqkv_lo, g_qkv, QKV_COLS);
}

__global__ void __launch_bounds__(256, 2) k_oproj(float* __restrict__ out)
{
    gemm_v3(g_ao_hi, g_ao_lo, g_wo_hi, g_wo_lo, out, HID);
}

// ---------------------------------------------------------------------------
// RoPE + split + repack q/k/v (q folded with scale*log2e).
// ---------------------------------------------------------------------------
__global__ void __launch_bounds__(256) k_rope_split(const float* __restrict__ cosp,
                                                    const float* __restrict__ sinp)
{
    const int d = threadIdx.x & 63;
    const int row = blockIdx.x * 4 + (threadIdx.x >> 6);
    const int head = blockIdx.y;
    const int s = row & (SEQ - 1);
    const int b = row >> 11;

    const float* p = g_qkv + (size_t)row * QKV_COLS + head * HD;
    float x1 = p[d];
    float x2 = p[d + 64];
    float y1, y2;
    if (head < 32) {
        float c1 = cosp[s * HD + d],      s1 = sinp[s * HD + d];
        float c2 = cosp[s * HD + d + 64], s2 = sinp[s * HD + d + 64];
        y1 = x1 * c1 - x2 * s1;
        y2 = x2 * c2 + x1 * s2;
    } else { y1 = x1; y2 = x2; }

    u16 *dh, *dl;
    int h;
    if (head < 16)      { h = head;      dh = g_q_hi; dl = g_q_lo; y1 *= QSCALE; y2 *= QSCALE; }
    else if (head < 32) { h = head - 16; dh = g_k_hi; dl = g_k_lo; }
    else                { h = head - 32; dh = g_v_hi; dl = g_v_lo; }

    const size_t base = ((size_t)(b * NH + h) * SEQ + s) * HD;
    __nv_bfloat16 h1 = __float2bfloat16_rn(y1);
    __nv_bfloat16 h2 = __float2bfloat16_rn(y2);
    dh[base + d]      = __bfloat16_as_ushort(h1);
    dh[base + d + 64] = __bfloat16_as_ushort(h2);
    dl[base + d]      = __bfloat16_as_ushort(__float2bfloat16_rn(y1 - __bfloat162float(h1)));
    dl[base + d + 64] = __bfloat16_as_ushort(__float2bfloat16_rn(y2 - __bfloat162float(h2)));
}

// ---------------------------------------------------------------------------
// Flash attention (unchanged from R4).
// ---------------------------------------------------------------------------
#define FSTR 272
#define QTILE 34816
#define KVT   17408
#define KVBUF 69632
#define FSMEM 208896

__global__ void __launch_bounds__(256, 1) k_flash()
{
    extern __shared__ __align__(16) unsigned char dsm[];
    const int tid = threadIdx.x, lane = tid & 31, w = tid >> 5;
    const int qb = blockIdx.x, z = blockIdx.y;
    const int b = z >> 4, h = z & 15;

    const uint32_t smQh = smem_u32(dsm);
    const uint32_t smQl = smQh + QTILE;
    const uint32_t smKV = smQh + 2 * QTILE;

    const size_t zbase = (size_t)z * SEQ * HD;
    const u16* gqh = g_q_hi + zbase + (size_t)qb * 128 * HD;
    const u16* gql = g_q_lo + zbase + (size_t)qb * 128 * HD;
    const u16* gkh = g_k_hi + zbase;
    const u16* gkl = g_k_lo + zbase;
    const u16* gvh = g_v_hi + zbase;
    const u16* gvl = g_v_lo + zbase;

    {
        const int ch0 = tid;
#pragma unroll
        for (int i = 0; i < 8; i++) {
            int ch = i * 256 + ch0;
            int r = ch >> 4, q = ch & 15;
            CP_ASYNC16(smQh + r * FSTR + q * 16, gqh + r * HD + q * 8);
            CP_ASYNC16(smQl + r * FSTR + q * 16, gql + r * HD + q * 8);
        }
    }
#define LOAD_KV(t, buf) do { \
        uint32_t kb = smKV + (buf) * KVBUF; \
        const size_t rb = (size_t)(t) * 64; \
        _Pragma("unroll") \
        for (int i = 0; i < 4; i++) { \
            int ch = i * 256 + tid; \
            int r = ch >> 4, q = ch & 15; \
            uint32_t so = r * FSTR + q * 16; \
            size_t go = (rb + r) * HD + q * 8; \
            CP_ASYNC16(kb + so,            gkh + go); \
            CP_ASYNC16(kb + KVT + so,      gkl + go); \
            CP_ASYNC16(kb + 2 * KVT + so,  gvh + go); \
            CP_ASYNC16(kb + 3 * KVT + so,  gvl + go); \
        } \
    } while (0)

    LOAD_KV(0, 0);
    CP_COMMIT();

    const uint32_t a_off = (uint32_t)(w * 16 + (lane & 15)) * FSTR + ((lane >> 4) * 16);
    const uint32_t kb_off = (uint32_t)(((lane >> 4) & 1) * 8 + (lane & 7)) * FSTR
                          + (((lane >> 3) & 1) * 16);
    const uint32_t v_off = (uint32_t)(((lane >> 3) & 1) * 8 + (lane & 7)) * FSTR
                         + (((lane >> 4) & 1) * 16);

    float o[16][4] = {};
    float m0 = -1e30f, m1 = -1e30f, l0 = 0.0f, l1 = 0.0f;

    for (int t = 0; t < 32; t++) {
        if (t + 1 < 32) LOAD_KV(t + 1, (t + 1) & 1);
        CP_COMMIT();
        if (t + 1 < 32) { CP_WAIT1(); } else { CP_WAIT0(); }
        __syncthreads();

        const uint32_t kb = smKV + (t & 1) * KVBUF;
        const uint32_t sKh = kb + kb_off;
        const uint32_t sKl = kb + KVT + kb_off;
        const uint32_t sVh = kb + 2 * KVT + v_off;
        const uint32_t sVl = kb + 3 * KVT + v_off;
        const uint32_t sQh = smQh + a_off;
        const uint32_t sQl = smQl + a_off;

        float sf[8][4] = {};
#pragma unroll
        for (int c = 0; c < 8; c++) {
            uint32_t qh[4], ql[4];
            LDSM_X4(qh[0], qh[1], qh[2], qh[3], sQh + c * 32);
            LDSM_X4(ql[0], ql[1], ql[2], ql[3], sQl + c * 32);
#pragma unroll
            for (int p = 0; p < 4; p++) {
                uint32_t kh[4], kl[4];
                LDSM_X4(kh[0], kh[1], kh[2], kh[3], sKh + p * 16 * FSTR + c * 32);
                LDSM_X4(kl[0], kl[1], kl[2], kl[3], sKl + p * 16 * FSTR + c * 32);
                MMA16816(sf[2*p],   qh, kh[0], kh[1]);
                MMA16816(sf[2*p],   qh, kl[0], kl[1]);
                MMA16816(sf[2*p],   ql, kh[0], kh[1]);
                MMA16816(sf[2*p+1], qh, kh[2], kh[3]);
                MMA16816(sf[2*p+1], qh, kl[2], kl[3]);
                MMA16816(sf[2*p+1], ql, kh[2], kh[3]);
            }
        }

        float tm0 = -1e30f, tm1 = -1e30f;
#pragma unroll
        for (int e = 0; e < 8; e++) {
            tm0 = fmaxf(tm0, fmaxf(sf[e][0], sf[e][1]));
            tm1 = fmaxf(tm1, fmaxf(sf[e][2], sf[e][3]));
        }
        tm0 = fmaxf(tm0, __shfl_xor_sync(0xffffffffu, tm0, 1));
        tm0 = fmaxf(tm0, __shfl_xor_sync(0xffffffffu, tm0, 2));
        tm1 = fmaxf(tm1, __shfl_xor_sync(0xffffffffu, tm1, 1));
        tm1 = fmaxf(tm1, __shfl_xor_sync(0xffffffffu, tm1, 2));
        const float m0n = fmaxf(m0, tm0), m1n = fmaxf(m1, tm1);
        const float c0 = exp2f(m0 - m0n), c1 = exp2f(m1 - m1n);
        float ts0 = 0.0f, ts1 = 0.0f;
#pragma unroll
        for (int e = 0; e < 8; e++) {
            sf[e][0] = exp2f(sf[e][0] - m0n);
            sf[e][1] = exp2f(sf[e][1] - m0n);
            sf[e][2] = exp2f(sf[e][2] - m1n);
            sf[e][3] = exp2f(sf[e][3] - m1n);
            ts0 += sf[e][0] + sf[e][1];
            ts1 += sf[e][2] + sf[e][3];
        }
        ts0 += __shfl_xor_sync(0xffffffffu, ts0, 1);
        ts0 += __shfl_xor_sync(0xffffffffu, ts0, 2);
        ts1 += __shfl_xor_sync(0xffffffffu, ts1, 1);
        ts1 += __shfl_xor_sync(0xffffffffu, ts1, 2);
        l0 = l0 * c0 + ts0;
        l1 = l1 * c1 + ts1;
        m0 = m0n; m1 = m1n;
#pragma unroll
        for (int f = 0; f < 16; f++) {
            o[f][0] *= c0; o[f][1] *= c0;
            o[f][2] *= c1; o[f][3] *= c1;
        }

#pragma unroll
        for (int j = 0; j < 4; j++) {
            uint32_t ah[4], al[4];
            split2(sf[2*j][0],   sf[2*j][1],   ah[0], al[0]);
            split2(sf[2*j][2],   sf[2*j][3],   ah[1], al[1]);
            split2(sf[2*j+1][0], sf[2*j+1][1], ah[2], al[2]);
            split2(sf[2*j+1][2], sf[2*j+1][3], ah[3], al[3]);
#pragma unroll
            for (int f = 0; f < 8; f++) {
                uint32_t vh[4], vl[4];
                LDSM_X4_T(vh[0], vh[1], vh[2], vh[3], sVh + j * 16 * FSTR + f * 32);
                LDSM_X4_T(vl[0], vl[1], vl[2], vl[3], sVl + j * 16 * FSTR + f * 32);
                MMA16816(o[2*f],   ah, vh[0], vh[1]);
                MMA16816(o[2*f],   ah, vl[0], vl[1]);
                MMA16816(o[2*f],   al, vh[0], vh[1]);
                MMA16816(o[2*f+1], ah, vh[2], vh[3]);
                MMA16816(o[2*f+1], ah, vl[2], vl[3]);
                MMA16816(o[2*f+1], al, vh[2], vh[3]);
            }
        }
        __syncthreads();
    }
#undef LOAD_KV

    const float inv0 = 1.0f / l0, inv1 = 1.0f / l1;
    const size_t row0 = (size_t)(b * SEQ + qb * 128 + w * 16 + (lane >> 2));
    const size_t colb = (size_t)h * HD + (lane & 3) * 2;
#pragma unroll
    for (int f = 0; f < 16; f++) {
        uint32_t h01, l01, h23, l23;
        split2(o[f][0] * inv0, o[f][1] * inv0, h01, l01);
        split2(o[f][2] * inv1, o[f][3] * inv1, h23, l23);
        size_t i0 = row0 * HID + colb + f * 8;
        size_t i1 = i0 + (size_t)8 * HID;
        *(uint32_t*)(g_ao_hi + i0) = h01;
        *(uint32_t*)(g_ao_lo + i0) = l01;
        *(uint32_t*)(g_ao_hi + i1) = h23;
        *(uint32_t*)(g_ao_lo + i1) = l23;
    }
}

// ---------------------------------------------------------------------------
// Launch
// ---------------------------------------------------------------------------
extern "C" void kernel_launch(void* const* d_in, const int* in_sizes, int n_in,
                              void* d_out, int out_size)
{
    const float* hidden = (const float*)d_in[0];
    const float* cosp   = (const float*)d_in[1];
    const float* sinp   = (const float*)d_in[2];
    const float* wqkv   = (const float*)d_in[3];
    const float* wo     = (const float*)d_in[4];
    float* out = (float*)d_out;

    cudaFuncSetAttribute(k_flash, cudaFuncAttributeMaxDynamicSharedMemorySize, FSMEM);
    cudaFuncSetAttribute(k_qkv,   cudaFuncAttributeMaxDynamicSharedMemorySize, GSMEM);
    cudaFuncSetAttribute(k_oproj, cudaFuncAttributeMaxDynamicSharedMemorySize, GSMEM);

    u16 *hh, *hl, *wh, *wl, *oh, *ol;
    cudaGetSymbolAddress((void**)&hh, g_h_hi);
    cudaGetSymbolAddress((void**)&hl, g_h_lo);
    cudaGetSymbolAddress((void**)&wh, g_wqkv_hi);
    cudaGetSymbolAddress((void**)&wl, g_wqkv_lo);
    cudaGetSymbolAddress((void**)&oh, g_wo_hi);
    cudaGetSymbolAddress((void**)&ol, g_wo_lo);

    k_split<<<(ROWS * HID) / 1024, 256>>>(hidden, hh, hl);
    k_split<<<(QKV_COLS * HID) / 1024, 256>>>(wqkv, wh, wl);
    k_split<<<(HID * HID) / 1024, 256>>>(wo, oh, ol);

    k_qkv<<<dim3(QKV_COLS / 128, ROWS / 128), 256, GSMEM>>>();
    k_rope_split<<<dim3(1024, 48), 256>>>(cosp, sinp);
    k_flash<<<dim3(16, 32), 256, FSMEM>>>();
    k_oproj<<<dim3(HID / 128, ROWS / 128), 256, GSMEM>>>(out);
}